// round 14
// baseline (speedup 1.0000x reference)
#include <cuda_runtime.h>
#include <cuda_fp16.h>
#include <cuda_bf16.h>

// ---------------------------------------------------------------------------
// GAT (2-layer, H=4, D=32, IN=128) on GB300, round 13.
//  - GEMM reverted to R11 config (grid=782, 1 tile/block, W copied per block;
//    measured 27.1us vs 30.0us for the 2-tile loop).
//  - CSR build compressed into ONE persistent cooperative kernel (4 grid
//    barriers), replacing 5 small launches.
//  - 6 launches total; k_agg<1> lands in the profiled 4th slot.
// ---------------------------------------------------------------------------

#define NN 50000
#define EE 800000
#define FDIM 128
#define NEG_SLOPE 0.2f
#define MB 64                  // GEMM rows per block
#define KPAD 136               // padded smem row (halves); 272B stride
#define NGEMM ((NN + MB - 1) / MB)     // 782
#define NSEG 196                       // ceil(50000/256)
#define CSR_GRID 296                   // 148 SMs x 2, all co-resident
#define CSR_TPB 256

typedef unsigned long long ull;

// -------------------- scratch (static device globals) ----------------------
__device__ __half g_feat_h[NN * FDIM];   // 12.8 MB fp16 features, head-interleaved
__device__ float  g_h1[NN * FDIM];       // 25.6 MB layer-1 output
__device__ __half g_Wh[2][FDIM * FDIM];  // 64 KB   fp16 weights (pre-converted)
__device__ int    g_csr_src[EE];         //  3.2 MB
__device__ int    g_cnt[NN];
__device__ int    g_row[NN];
__device__ int    g_pos[NN];
__device__ float  g_el[NN * 4];
__device__ float  g_er[NN * 4];
__device__ int    g_bsum[NSEG];
__device__ int    g_bar_count;           // zero-init; returns to 0 each launch
__device__ int    g_bar_sense;           // 4 barriers (even) -> returns to 0

// -------------------- math helpers ------------------------------------------
__device__ __forceinline__ float lrelu(float x) { return x > 0.f ? x : NEG_SLOPE * x; }
__device__ __forceinline__ float elu1(float x)  { return x > 0.f ? x : (__expf(x) - 1.f); }

__device__ __forceinline__ unsigned smaddr(const void* p) {
    return (unsigned)__cvta_generic_to_shared(p);
}
__device__ __forceinline__ void ldsm_x4(unsigned* r, unsigned addr) {
    asm volatile("ldmatrix.sync.aligned.m8n8.x4.shared.b16 {%0,%1,%2,%3}, [%4];"
                 : "=r"(r[0]), "=r"(r[1]), "=r"(r[2]), "=r"(r[3]) : "r"(addr));
}
__device__ __forceinline__ void ldsm_x4_t(unsigned* r, unsigned addr) {
    asm volatile("ldmatrix.sync.aligned.m8n8.x4.trans.shared.b16 {%0,%1,%2,%3}, [%4];"
                 : "=r"(r[0]), "=r"(r[1]), "=r"(r[2]), "=r"(r[3]) : "r"(addr));
}
__device__ __forceinline__ void mma16816(float* d, const unsigned* a, const unsigned* b) {
    asm volatile("mma.sync.aligned.m16n8k16.row.col.f32.f16.f16.f32 "
                 "{%0,%1,%2,%3}, {%4,%5,%6,%7}, {%8,%9}, {%0,%1,%2,%3};"
                 : "+f"(d[0]), "+f"(d[1]), "+f"(d[2]), "+f"(d[3])
                 : "r"(a[0]), "r"(a[1]), "r"(a[2]), "r"(a[3]), "r"(b[0]), "r"(b[1]));
}

// -------------------- weight pre-convert (both layers, one launch) ----------
__global__ void k_wconv(const float* __restrict__ W1, const float* __restrict__ W2) {
    int i = blockIdx.x * blockDim.x + threadIdx.x;      // over 2*4096 float4
    if (i >= 2 * FDIM * FDIM / 4) return;
    int slot = i >= FDIM * FDIM / 4;
    int j = i - slot * (FDIM * FDIM / 4);
    const float* W = slot ? W2 : W1;
    float4 v = reinterpret_cast<const float4*>(W)[j];
    reinterpret_cast<__half2*>(g_Wh[slot])[j * 2]     = __floats2half2_rn(v.x, v.y);
    reinterpret_cast<__half2*>(g_Wh[slot])[j * 2 + 1] = __floats2half2_rn(v.z, v.w);
}

// -------------------- persistent CSR build (one kernel) ---------------------
struct CsrSm {
    int warp[8];
    int woff[8];
    int segoff[256];
    int bsense;
};

__device__ __forceinline__ void csr_gbar(CsrSm* sm) {
    __syncthreads();
    if (threadIdx.x == 0) {
        int want = sm->bsense ^ 1;
        __threadfence();
        int a = atomicAdd(&g_bar_count, 1);
        if (a == CSR_GRID - 1) {
            atomicExch(&g_bar_count, 0);
            __threadfence();
            atomicExch(&g_bar_sense, want);
        } else {
            while (*(volatile int*)&g_bar_sense != want) __nanosleep(64);
        }
        __threadfence();
        sm->bsense = want;
    }
    __syncthreads();
}

// exclusive block scan over 256 ints (one value per thread)
__device__ __forceinline__ int blockscan256(CsrSm* sm, int v) {
    int t = threadIdx.x, lane = t & 31, w = t >> 5;
    int x = v;
#pragma unroll
    for (int off = 1; off < 32; off <<= 1) {
        int y = __shfl_up_sync(0xffffffffu, x, off);
        if (lane >= off) x += y;
    }
    if (lane == 31) sm->warp[w] = x;
    __syncthreads();
    if (t < 8) {
        int y = sm->warp[t];
        int z = y;
#pragma unroll
        for (int off = 1; off < 8; off <<= 1) {
            int q = __shfl_up_sync(0xffu, z, off);
            if (t >= off) z += q;
        }
        sm->woff[t] = z - y;
    }
    __syncthreads();
    return x - v + sm->woff[w];
}

__global__ void __launch_bounds__(CSR_TPB) k_csr(const int* __restrict__ src,
                                                 const int* __restrict__ dst) {
    __shared__ CsrSm sm;
    int bid = blockIdx.x, t = threadIdx.x;
    if (t == 0) sm.bsense = 0;
    __syncthreads();

    // P0: zero counts
    for (int i = bid * CSR_TPB + t; i < NN; i += CSR_GRID * CSR_TPB) g_cnt[i] = 0;
    csr_gbar(&sm);                                                   // B1

    // P1: degree count
    for (int e = bid * CSR_TPB + t; e < EE; e += CSR_GRID * CSR_TPB)
        atomicAdd(&g_cnt[dst[e]], 1);
    csr_gbar(&sm);                                                   // B2

    // P2: per-segment exclusive scan (segment = 256 nodes)
    if (bid < NSEG) {
        int i = bid * CSR_TPB + t;
        int v = (i < NN) ? g_cnt[i] : 0;
        int ex = blockscan256(&sm, v);
        if (i < NN) g_row[i] = ex;                 // segment-local exclusive
        if (t == CSR_TPB - 1) g_bsum[bid] = ex + v;
    }
    csr_gbar(&sm);                                                   // B3

    // P3: add segment offsets (every block computes the 196-prefix itself)
    {
        int v = (t < NSEG) ? g_bsum[t] : 0;
        int ex = blockscan256(&sm, v);
        sm.segoff[t] = ex;
        __syncthreads();
        if (bid < NSEG) {
            int i = bid * CSR_TPB + t;
            if (i < NN) {
                int r = g_row[i] + sm.segoff[bid];
                g_row[i] = r;
                g_pos[i] = r;
            }
        }
    }
    csr_gbar(&sm);                                                   // B4

    // P4: scatter edges
    for (int e = bid * CSR_TPB + t; e < EE; e += CSR_GRID * CSR_TPB) {
        int d = dst[e];
        int p = atomicAdd(&g_pos[d], 1);
        g_csr_src[p] = src[e];
    }
}

// -------------------- tensor-core GEMM + el/er + fp16 emit (R11) ------------
__global__ void __launch_bounds__(256, 3) k_gemm_fused(const float* __restrict__ X,
                                                       const __half* __restrict__ Wh,
                                                       const float* __restrict__ al,
                                                       const float* __restrict__ ar) {
    __shared__ __half Xp[MB][KPAD];      // 17408 B ; epilogue reuses as Hs
    __shared__ __half Wp[FDIM][KPAD];    // 34816 B

    int t = threadIdx.x;
    int lane = t & 31, wid = t >> 5;
    int row0 = blockIdx.x * MB;

    // ---- fill smem ----
#pragma unroll
    for (int it = 0; it < 8; it++) {
        int i = t + it * 256;
        int r = i >> 5, c4 = (i & 31) * 4;
        int gr = row0 + r;
        float4 v = (gr < NN) ? *reinterpret_cast<const float4*>(&X[gr * FDIM + c4])
                             : make_float4(0.f, 0.f, 0.f, 0.f);
        *reinterpret_cast<__half2*>(&Xp[r][c4])     = __floats2half2_rn(v.x, v.y);
        *reinterpret_cast<__half2*>(&Xp[r][c4 + 2]) = __floats2half2_rn(v.z, v.w);
    }
#pragma unroll
    for (int it = 0; it < 8; it++) {
        int i = t + it * 256;
        int r = i >> 4, c8 = (i & 15) * 8;
        *reinterpret_cast<uint4*>(&Wp[r][c8]) =
            reinterpret_cast<const uint4*>(Wh + r * FDIM)[c8 >> 3];
    }
    __syncthreads();

    int wm = wid & 3, wn = wid >> 2;
    float acc[8][4];
#pragma unroll
    for (int u = 0; u < 8; u++)
#pragma unroll
        for (int c = 0; c < 4; c++) acc[u][c] = 0.f;

#pragma unroll
    for (int kk = 0; kk < 8; kk++) {
        unsigned A[4];
        {
            int r = wm * 16 + (lane & 15);
            int k = kk * 16 + ((lane >> 4) & 1) * 8;
            ldsm_x4(A, smaddr(&Xp[r][k]));
        }
        unsigned B[8][2];
#pragma unroll
        for (int ub = 0; ub < 4; ub++) {
            int kloc = kk * 16 + (lane & 7) + ((lane >> 3) & 1) * 8;
            int col = wn * 64 + (ub * 2 + ((lane >> 4) & 1)) * 8;
            unsigned r4[4];
            ldsm_x4_t(r4, smaddr(&Wp[kloc][col]));
            B[2 * ub][0] = r4[0]; B[2 * ub][1] = r4[1];
            B[2 * ub + 1][0] = r4[2]; B[2 * ub + 1][1] = r4[3];
        }
#pragma unroll
        for (int u = 0; u < 8; u++) mma16816(acc[u], A, B[u]);
    }
    __syncthreads();   // all reads of Xp/Wp done before Hs overwrite

    // ---- epilogue: head-interleaved fp16 emit into Hs (= Xp) ----
    __half (*Hs)[KPAD] = Xp;
#pragma unroll
    for (int u = 0; u < 8; u++) {
        int R = wm * 16 + (lane >> 2);
        int C = wn * 64 + u * 8 + (lane & 3) * 2;
        int p0 = ((C & 31) << 2) | (C >> 5);           // head-interleave
        Hs[R][p0]         = __float2half(acc[u][0]);
        Hs[R][p0 + 4]     = __float2half(acc[u][1]);
        Hs[R + 8][p0]     = __float2half(acc[u][2]);
        Hs[R + 8][p0 + 4] = __float2half(acc[u][3]);
    }
    __syncthreads();

    // ---- el/er: warp wid handles rows wid*8..+7 ----
    float alv[4], arv[4];
#pragma unroll
    for (int h = 0; h < 4; h++) {
        alv[h] = al[h * 32 + lane];
        arv[h] = ar[h * 32 + lane];
    }
#pragma unroll
    for (int i = 0; i < 8; i++) {
        int R = wid * 8 + i;
        int gr = row0 + R;
        uint2 uu = *reinterpret_cast<const uint2*>(&Hs[R][lane * 4]);
        float2 q0 = __half22float2(*reinterpret_cast<__half2*>(&uu.x));
        float2 q1 = __half22float2(*reinterpret_cast<__half2*>(&uu.y));
        float v0 = q0.x, v1 = q0.y, v2 = q1.x, v3 = q1.y;
        float l0 = v0 * alv[0], l1 = v1 * alv[1], l2 = v2 * alv[2], l3 = v3 * alv[3];
        float r0 = v0 * arv[0], r1 = v1 * arv[1], r2 = v2 * arv[2], r3 = v3 * arv[3];
#pragma unroll
        for (int off = 16; off; off >>= 1) {
            l0 += __shfl_xor_sync(0xffffffffu, l0, off);
            l1 += __shfl_xor_sync(0xffffffffu, l1, off);
            l2 += __shfl_xor_sync(0xffffffffu, l2, off);
            l3 += __shfl_xor_sync(0xffffffffu, l3, off);
            r0 += __shfl_xor_sync(0xffffffffu, r0, off);
            r1 += __shfl_xor_sync(0xffffffffu, r1, off);
            r2 += __shfl_xor_sync(0xffffffffu, r2, off);
            r3 += __shfl_xor_sync(0xffffffffu, r3, off);
        }
        if (lane == 0 && gr < NN) {
            g_el[gr * 4 + 0] = l0; g_el[gr * 4 + 1] = l1;
            g_el[gr * 4 + 2] = l2; g_el[gr * 4 + 3] = l3;
            g_er[gr * 4 + 0] = r0; g_er[gr * 4 + 1] = r1;
            g_er[gr * 4 + 2] = r2; g_er[gr * 4 + 3] = r3;
        }
    }

    // ---- coalesced fp16 feature write-out ----
#pragma unroll
    for (int it = 0; it < 4; it++) {
        int i = t + it * 256;
        int r = i >> 4, c = i & 15;
        int gr = row0 + r;
        if (gr < NN)
            reinterpret_cast<uint4*>(g_feat_h + (size_t)gr * FDIM)[c] =
                *reinterpret_cast<const uint4*>(&Hs[r][c * 8]);
    }
}

// -------------------- single-pass warp-per-node softmax + SpMM --------------
#define AGG_WARPS 8

// MODE 1: layer1 -> elu, 128 feats (fp32) to g_h1. MODE 2: head-mean to out.
template <int MODE>
__global__ void __launch_bounds__(AGG_WARPS * 32) k_agg(const float* __restrict__ resid,
                                                        const float* __restrict__ bias,
                                                        float* __restrict__ out) {
    __shared__ __align__(16) float4 sm_w[AGG_WARPS][33];
    __shared__ int sm_s[AGG_WARPS][32];

    int wid  = threadIdx.x >> 5;
    int lane = threadIdx.x & 31;
    int node = blockIdx.x * AGG_WARPS + wid;
    if (node >= NN) return;

    int base = g_row[node];
    int deg  = g_cnt[node];
    float4 er4 = reinterpret_cast<const float4*>(g_er)[node];

    float sx = 0.f, sy = 0.f, sz = 0.f, sw = 0.f;
    float a0 = 0.f, a1 = 0.f, a2 = 0.f, a3 = 0.f;

    for (int c0 = 0; c0 < deg; c0 += 32) {
        int m = deg - c0; if (m > 32) m = 32;
        if (lane < m) {
            int s = g_csr_src[base + c0 + lane];
            float4 l4 = reinterpret_cast<const float4*>(g_el)[s];
            float4 w4;
            w4.x = __expf(lrelu(l4.x + er4.x));
            w4.y = __expf(lrelu(l4.y + er4.y));
            w4.z = __expf(lrelu(l4.z + er4.z));
            w4.w = __expf(lrelu(l4.w + er4.w));
            sx += w4.x; sy += w4.y; sz += w4.z; sw += w4.w;
            sm_s[wid][lane] = s;
            sm_w[wid][lane] = w4;
        }
        __syncwarp();
        int j = 0;
        for (; j + 3 < m; j += 4) {
            int   s0 = sm_s[wid][j];
            int   s1 = sm_s[wid][j + 1];
            int   s2 = sm_s[wid][j + 2];
            int   s3 = sm_s[wid][j + 3];
            float4 w0 = sm_w[wid][j];
            float4 w1 = sm_w[wid][j + 1];
            float4 w2 = sm_w[wid][j + 2];
            float4 w3 = sm_w[wid][j + 3];
            uint2 u0 = *reinterpret_cast<const uint2*>(g_feat_h + (size_t)s0 * FDIM + lane * 4);
            uint2 u1 = *reinterpret_cast<const uint2*>(g_feat_h + (size_t)s1 * FDIM + lane * 4);
            uint2 u2 = *reinterpret_cast<const uint2*>(g_feat_h + (size_t)s2 * FDIM + lane * 4);
            uint2 u3 = *reinterpret_cast<const uint2*>(g_feat_h + (size_t)s3 * FDIM + lane * 4);
            float2 f00 = __half22float2(*reinterpret_cast<__half2*>(&u0.x));
            float2 f01 = __half22float2(*reinterpret_cast<__half2*>(&u0.y));
            float2 f10 = __half22float2(*reinterpret_cast<__half2*>(&u1.x));
            float2 f11 = __half22float2(*reinterpret_cast<__half2*>(&u1.y));
            float2 f20 = __half22float2(*reinterpret_cast<__half2*>(&u2.x));
            float2 f21 = __half22float2(*reinterpret_cast<__half2*>(&u2.y));
            float2 f30 = __half22float2(*reinterpret_cast<__half2*>(&u3.x));
            float2 f31 = __half22float2(*reinterpret_cast<__half2*>(&u3.y));
            a0 += w0.x * f00.x + w1.x * f10.x + w2.x * f20.x + w3.x * f30.x;
            a1 += w0.y * f00.y + w1.y * f10.y + w2.y * f20.y + w3.y * f30.y;
            a2 += w0.z * f01.x + w1.z * f11.x + w2.z * f21.x + w3.z * f31.x;
            a3 += w0.w * f01.y + w1.w * f11.y + w2.w * f21.y + w3.w * f31.y;
        }
        for (; j < m; j++) {
            int   s0 = sm_s[wid][j];
            float4 w0 = sm_w[wid][j];
            uint2 u0 = *reinterpret_cast<const uint2*>(g_feat_h + (size_t)s0 * FDIM + lane * 4);
            float2 f00 = __half22float2(*reinterpret_cast<__half2*>(&u0.x));
            float2 f01 = __half22float2(*reinterpret_cast<__half2*>(&u0.y));
            a0 += w0.x * f00.x;
            a1 += w0.y * f00.y;
            a2 += w0.z * f01.x;
            a3 += w0.w * f01.y;
        }
        __syncwarp();
    }

#pragma unroll
    for (int off = 16; off; off >>= 1) {
        sx += __shfl_xor_sync(0xffffffffu, sx, off);
        sy += __shfl_xor_sync(0xffffffffu, sy, off);
        sz += __shfl_xor_sync(0xffffffffu, sz, off);
        sw += __shfl_xor_sync(0xffffffffu, sw, off);
    }
    float invx = 1.f / fmaxf(sx, 1e-9f);
    float invy = 1.f / fmaxf(sy, 1e-9f);
    float invz = 1.f / fmaxf(sz, 1e-9f);
    float invw = 1.f / fmaxf(sw, 1e-9f);

    float r0 = a0 * invx + resid[node * FDIM + 0  + lane] + bias[0  + lane];
    float r1 = a1 * invy + resid[node * FDIM + 32 + lane] + bias[32 + lane];
    float r2 = a2 * invz + resid[node * FDIM + 64 + lane] + bias[64 + lane];
    float r3 = a3 * invw + resid[node * FDIM + 96 + lane] + bias[96 + lane];

    if (MODE == 1) {
        out[node * FDIM + 0  + lane] = elu1(r0);
        out[node * FDIM + 32 + lane] = elu1(r1);
        out[node * FDIM + 64 + lane] = elu1(r2);
        out[node * FDIM + 96 + lane] = elu1(r3);
    } else {
        out[node * 32 + lane] = 0.25f * (r0 + r1 + r2 + r3);
    }
}

// -------------------- launch ------------------------------------------------
extern "C" void kernel_launch(void* const* d_in, const int* in_sizes, int n_in,
                              void* d_out, int out_size) {
    const float* x   = (const float*)d_in[0];
    const float* W1  = (const float*)d_in[1];
    const float* al1 = (const float*)d_in[2];
    const float* ar1 = (const float*)d_in[3];
    const float* b1  = (const float*)d_in[4];
    const float* W2  = (const float*)d_in[5];
    const float* al2 = (const float*)d_in[6];
    const float* ar2 = (const float*)d_in[7];
    const float* b2  = (const float*)d_in[8];
    const int*   src = (const int*)d_in[9];
    const int*   dst = (const int*)d_in[10];
    float* out = (float*)d_out;

    float* h1 = nullptr;
    __half* wh = nullptr;
    cudaGetSymbolAddress((void**)&h1, g_h1);
    cudaGetSymbolAddress((void**)&wh, g_Wh);

    const int TB = 256;
    int nAgg = (NN + AGG_WARPS - 1) / AGG_WARPS;      // 6250
    int nWc  = (2 * FDIM * FDIM / 4 + TB - 1) / TB;   // 32

    k_wconv<<<nWc, TB>>>(W1, W2);                           // 1
    k_csr<<<CSR_GRID, CSR_TPB>>>(src, dst);                 // 2
    k_gemm_fused<<<NGEMM, 256>>>(x, wh, al1, ar1);          // 3
    k_agg<1><<<nAgg, AGG_WARPS * 32>>>(x, b1, h1);          // 4  <- profiled
    k_gemm_fused<<<NGEMM, 256>>>(h1, wh + FDIM * FDIM, al2, ar2); // 5
    k_agg<2><<<nAgg, AGG_WARPS * 32>>>(h1, b2, out);        // 6
}

// round 15
// speedup vs baseline: 1.1278x; 1.1278x over previous
#include <cuda_runtime.h>
#include <cuda_fp16.h>
#include <cuda_bf16.h>

// ---------------------------------------------------------------------------
// GAT (2-layer, H=4, D=32, IN=128) on GB300, round 15.
// Base = R12 (best, 164.6us) with:
//  - GEMM = R11 1-tile config (measured 27.1us vs 30.0us for 2-tile)
//  - agg  = grid-stride persistent warps (592 blocks = 148 SMs x 4 resident;
//    kills the 6250-block churn behind occ 43% / issue 45% in the R14 profile)
//  - CSR = separate kernels with folded segment-scan (unchanged from R12)
// ---------------------------------------------------------------------------

#define NN 50000
#define EE 800000
#define FDIM 128
#define NEG_SLOPE 0.2f
#define MB 64                  // GEMM rows per block
#define KPAD 136               // padded smem row (halves); 272B stride
#define NGEMM ((NN + MB - 1) / MB)     // 782
#define NSCAN 49                       // ceil(50000/1024)
#define AGG_WARPS 8
#define AGG_GRID 592                   // 148 SMs x 4 blocks, all resident

typedef unsigned long long ull;

// -------------------- scratch (static device globals) ----------------------
__device__ __half g_feat_h[NN * FDIM];   // 12.8 MB fp16 features, head-interleaved
__device__ float  g_h1[NN * FDIM];       // 25.6 MB layer-1 output
__device__ __half g_Wh[2][FDIM * FDIM];  // 64 KB   fp16 weights (pre-converted)
__device__ int    g_csr_src[EE];         //  3.2 MB
__device__ int    g_cnt[NN];
__device__ int    g_row[NN];
__device__ int    g_pos[NN];
__device__ float  g_el[NN * 4];
__device__ float  g_er[NN * 4];
__device__ int    g_bsum[64];

// -------------------- math helpers ------------------------------------------
__device__ __forceinline__ float lrelu(float x) { return x > 0.f ? x : NEG_SLOPE * x; }
__device__ __forceinline__ float elu1(float x)  { return x > 0.f ? x : (__expf(x) - 1.f); }

__device__ __forceinline__ unsigned smaddr(const void* p) {
    return (unsigned)__cvta_generic_to_shared(p);
}
__device__ __forceinline__ void ldsm_x4(unsigned* r, unsigned addr) {
    asm volatile("ldmatrix.sync.aligned.m8n8.x4.shared.b16 {%0,%1,%2,%3}, [%4];"
                 : "=r"(r[0]), "=r"(r[1]), "=r"(r[2]), "=r"(r[3]) : "r"(addr));
}
__device__ __forceinline__ void ldsm_x4_t(unsigned* r, unsigned addr) {
    asm volatile("ldmatrix.sync.aligned.m8n8.x4.trans.shared.b16 {%0,%1,%2,%3}, [%4];"
                 : "=r"(r[0]), "=r"(r[1]), "=r"(r[2]), "=r"(r[3]) : "r"(addr));
}
__device__ __forceinline__ void mma16816(float* d, const unsigned* a, const unsigned* b) {
    asm volatile("mma.sync.aligned.m16n8k16.row.col.f32.f16.f16.f32 "
                 "{%0,%1,%2,%3}, {%4,%5,%6,%7}, {%8,%9}, {%0,%1,%2,%3};"
                 : "+f"(d[0]), "+f"(d[1]), "+f"(d[2]), "+f"(d[3])
                 : "r"(a[0]), "r"(a[1]), "r"(a[2]), "r"(a[3]), "r"(b[0]), "r"(b[1]));
}

// -------------------- weight pre-convert (both layers, one launch) ----------
__global__ void k_wconv(const float* __restrict__ W1, const float* __restrict__ W2) {
    int i = blockIdx.x * blockDim.x + threadIdx.x;      // over 2*4096 float4
    if (i >= 2 * FDIM * FDIM / 4) return;
    int slot = i >= FDIM * FDIM / 4;
    int j = i - slot * (FDIM * FDIM / 4);
    const float* W = slot ? W2 : W1;
    float4 v = reinterpret_cast<const float4*>(W)[j];
    reinterpret_cast<__half2*>(g_Wh[slot])[j * 2]     = __floats2half2_rn(v.x, v.y);
    reinterpret_cast<__half2*>(g_Wh[slot])[j * 2 + 1] = __floats2half2_rn(v.z, v.w);
}

// -------------------- CSR build --------------------------------------------
__global__ void k_zero_cnt() {
    int i = blockIdx.x * blockDim.x + threadIdx.x;
    if (i < NN) g_cnt[i] = 0;
}

__global__ void k_count(const int* __restrict__ dst) {
    int e = blockIdx.x * blockDim.x + threadIdx.x;
    if (e < EE) atomicAdd(&g_cnt[dst[e]], 1);
}

__global__ void k_scan1() {
    __shared__ int sm[1024];
    int i = blockIdx.x * 1024 + threadIdx.x;
    int v = (i < NN) ? g_cnt[i] : 0;
    sm[threadIdx.x] = v;
    __syncthreads();
#pragma unroll
    for (int off = 1; off < 1024; off <<= 1) {
        int t = (threadIdx.x >= off) ? sm[threadIdx.x - off] : 0;
        __syncthreads();
        sm[threadIdx.x] += t;
        __syncthreads();
    }
    if (i < NN) g_row[i] = sm[threadIdx.x] - v;
    if (threadIdx.x == 1023) g_bsum[blockIdx.x] = sm[1023];
}

// segment-offset scan folded in (49-elem prefix computed per block)
__global__ void k_scan3() {
    __shared__ int pre2[64];
    int t = threadIdx.x;
    if (t == 0) {
        int s = 0;
        for (int i = 0; i < NSCAN; i++) { int v = g_bsum[i]; pre2[i] = s; s += v; }
    }
    __syncthreads();
    int i = blockIdx.x * blockDim.x + t;
    if (i < NN) {
        int v = g_row[i] + pre2[i >> 10];
        g_row[i] = v;
        g_pos[i] = v;
    }
}

__global__ void k_scatter(const int* __restrict__ src, const int* __restrict__ dst) {
    int e = blockIdx.x * blockDim.x + threadIdx.x;
    if (e < EE) {
        int d = dst[e];
        int p = atomicAdd(&g_pos[d], 1);
        g_csr_src[p] = src[e];
    }
}

// -------------------- tensor-core GEMM + el/er + fp16 emit (R11 config) -----
__global__ void __launch_bounds__(256, 3) k_gemm_fused(const float* __restrict__ X,
                                                       const __half* __restrict__ Wh,
                                                       const float* __restrict__ al,
                                                       const float* __restrict__ ar) {
    __shared__ __half Xp[MB][KPAD];      // 17408 B ; epilogue reuses as Hs
    __shared__ __half Wp[FDIM][KPAD];    // 34816 B

    int t = threadIdx.x;
    int lane = t & 31, wid = t >> 5;
    int row0 = blockIdx.x * MB;

    // ---- fill smem ----
#pragma unroll
    for (int it = 0; it < 8; it++) {
        int i = t + it * 256;
        int r = i >> 5, c4 = (i & 31) * 4;
        int gr = row0 + r;
        float4 v = (gr < NN) ? *reinterpret_cast<const float4*>(&X[gr * FDIM + c4])
                             : make_float4(0.f, 0.f, 0.f, 0.f);
        *reinterpret_cast<__half2*>(&Xp[r][c4])     = __floats2half2_rn(v.x, v.y);
        *reinterpret_cast<__half2*>(&Xp[r][c4 + 2]) = __floats2half2_rn(v.z, v.w);
    }
#pragma unroll
    for (int it = 0; it < 8; it++) {
        int i = t + it * 256;
        int r = i >> 4, c8 = (i & 15) * 8;
        *reinterpret_cast<uint4*>(&Wp[r][c8]) =
            reinterpret_cast<const uint4*>(Wh + r * FDIM)[c8 >> 3];
    }
    __syncthreads();

    int wm = wid & 3, wn = wid >> 2;
    float acc[8][4];
#pragma unroll
    for (int u = 0; u < 8; u++)
#pragma unroll
        for (int c = 0; c < 4; c++) acc[u][c] = 0.f;

#pragma unroll
    for (int kk = 0; kk < 8; kk++) {
        unsigned A[4];
        {
            int r = wm * 16 + (lane & 15);
            int k = kk * 16 + ((lane >> 4) & 1) * 8;
            ldsm_x4(A, smaddr(&Xp[r][k]));
        }
        unsigned B[8][2];
#pragma unroll
        for (int ub = 0; ub < 4; ub++) {
            int kloc = kk * 16 + (lane & 7) + ((lane >> 3) & 1) * 8;
            int col = wn * 64 + (ub * 2 + ((lane >> 4) & 1)) * 8;
            unsigned r4[4];
            ldsm_x4_t(r4, smaddr(&Wp[kloc][col]));
            B[2 * ub][0] = r4[0]; B[2 * ub][1] = r4[1];
            B[2 * ub + 1][0] = r4[2]; B[2 * ub + 1][1] = r4[3];
        }
#pragma unroll
        for (int u = 0; u < 8; u++) mma16816(acc[u], A, B[u]);
    }
    __syncthreads();   // all reads of Xp/Wp done before Hs overwrite

    // ---- epilogue: head-interleaved fp16 emit into Hs (= Xp) ----
    __half (*Hs)[KPAD] = Xp;
#pragma unroll
    for (int u = 0; u < 8; u++) {
        int R = wm * 16 + (lane >> 2);
        int C = wn * 64 + u * 8 + (lane & 3) * 2;
        int p0 = ((C & 31) << 2) | (C >> 5);           // head-interleave
        Hs[R][p0]         = __float2half(acc[u][0]);
        Hs[R][p0 + 4]     = __float2half(acc[u][1]);
        Hs[R + 8][p0]     = __float2half(acc[u][2]);
        Hs[R + 8][p0 + 4] = __float2half(acc[u][3]);
    }
    __syncthreads();

    // ---- el/er: warp wid handles rows wid*8..+7 ----
    float alv[4], arv[4];
#pragma unroll
    for (int h = 0; h < 4; h++) {
        alv[h] = al[h * 32 + lane];
        arv[h] = ar[h * 32 + lane];
    }
#pragma unroll
    for (int i = 0; i < 8; i++) {
        int R = wid * 8 + i;
        int gr = row0 + R;
        uint2 uu = *reinterpret_cast<const uint2*>(&Hs[R][lane * 4]);
        float2 q0 = __half22float2(*reinterpret_cast<__half2*>(&uu.x));
        float2 q1 = __half22float2(*reinterpret_cast<__half2*>(&uu.y));
        float v0 = q0.x, v1 = q0.y, v2 = q1.x, v3 = q1.y;
        float l0 = v0 * alv[0], l1 = v1 * alv[1], l2 = v2 * alv[2], l3 = v3 * alv[3];
        float r0 = v0 * arv[0], r1 = v1 * arv[1], r2 = v2 * arv[2], r3 = v3 * arv[3];
#pragma unroll
        for (int off = 16; off; off >>= 1) {
            l0 += __shfl_xor_sync(0xffffffffu, l0, off);
            l1 += __shfl_xor_sync(0xffffffffu, l1, off);
            l2 += __shfl_xor_sync(0xffffffffu, l2, off);
            l3 += __shfl_xor_sync(0xffffffffu, l3, off);
            r0 += __shfl_xor_sync(0xffffffffu, r0, off);
            r1 += __shfl_xor_sync(0xffffffffu, r1, off);
            r2 += __shfl_xor_sync(0xffffffffu, r2, off);
            r3 += __shfl_xor_sync(0xffffffffu, r3, off);
        }
        if (lane == 0 && gr < NN) {
            g_el[gr * 4 + 0] = l0; g_el[gr * 4 + 1] = l1;
            g_el[gr * 4 + 2] = l2; g_el[gr * 4 + 3] = l3;
            g_er[gr * 4 + 0] = r0; g_er[gr * 4 + 1] = r1;
            g_er[gr * 4 + 2] = r2; g_er[gr * 4 + 3] = r3;
        }
    }

    // ---- coalesced fp16 feature write-out ----
#pragma unroll
    for (int it = 0; it < 4; it++) {
        int i = t + it * 256;
        int r = i >> 4, c = i & 15;
        int gr = row0 + r;
        if (gr < NN)
            reinterpret_cast<uint4*>(g_feat_h + (size_t)gr * FDIM)[c] =
                *reinterpret_cast<const uint4*>(&Hs[r][c * 8]);
    }
}

// -------------------- grid-stride warp-per-node softmax + SpMM --------------
// MODE 1: layer1 -> elu, 128 feats (fp32) to g_h1. MODE 2: head-mean to out.
template <int MODE>
__global__ void __launch_bounds__(AGG_WARPS * 32) k_agg(const float* __restrict__ resid,
                                                        const float* __restrict__ bias,
                                                        float* __restrict__ out) {
    __shared__ __align__(16) float4 sm_w[AGG_WARPS][33];
    __shared__ int sm_s[AGG_WARPS][32];

    int wid  = threadIdx.x >> 5;
    int lane = threadIdx.x & 31;

    for (int node = blockIdx.x * AGG_WARPS + wid; node < NN;
         node += AGG_GRID * AGG_WARPS) {

        int base = g_row[node];
        int deg  = g_cnt[node];
        float4 er4 = reinterpret_cast<const float4*>(g_er)[node];

        float sx = 0.f, sy = 0.f, sz = 0.f, sw = 0.f;
        float a0 = 0.f, a1 = 0.f, a2 = 0.f, a3 = 0.f;

        for (int c0 = 0; c0 < deg; c0 += 32) {
            int m = deg - c0; if (m > 32) m = 32;
            if (lane < m) {
                int s = g_csr_src[base + c0 + lane];
                float4 l4 = reinterpret_cast<const float4*>(g_el)[s];
                float4 w4;
                w4.x = __expf(lrelu(l4.x + er4.x));
                w4.y = __expf(lrelu(l4.y + er4.y));
                w4.z = __expf(lrelu(l4.z + er4.z));
                w4.w = __expf(lrelu(l4.w + er4.w));
                sx += w4.x; sy += w4.y; sz += w4.z; sw += w4.w;
                sm_s[wid][lane] = s;
                sm_w[wid][lane] = w4;
            }
            __syncwarp();
            int j = 0;
            for (; j + 3 < m; j += 4) {
                int   s0 = sm_s[wid][j];
                int   s1 = sm_s[wid][j + 1];
                int   s2 = sm_s[wid][j + 2];
                int   s3 = sm_s[wid][j + 3];
                float4 w0 = sm_w[wid][j];
                float4 w1 = sm_w[wid][j + 1];
                float4 w2 = sm_w[wid][j + 2];
                float4 w3 = sm_w[wid][j + 3];
                uint2 u0 = *reinterpret_cast<const uint2*>(g_feat_h + (size_t)s0 * FDIM + lane * 4);
                uint2 u1 = *reinterpret_cast<const uint2*>(g_feat_h + (size_t)s1 * FDIM + lane * 4);
                uint2 u2 = *reinterpret_cast<const uint2*>(g_feat_h + (size_t)s2 * FDIM + lane * 4);
                uint2 u3 = *reinterpret_cast<const uint2*>(g_feat_h + (size_t)s3 * FDIM + lane * 4);
                float2 f00 = __half22float2(*reinterpret_cast<__half2*>(&u0.x));
                float2 f01 = __half22float2(*reinterpret_cast<__half2*>(&u0.y));
                float2 f10 = __half22float2(*reinterpret_cast<__half2*>(&u1.x));
                float2 f11 = __half22float2(*reinterpret_cast<__half2*>(&u1.y));
                float2 f20 = __half22float2(*reinterpret_cast<__half2*>(&u2.x));
                float2 f21 = __half22float2(*reinterpret_cast<__half2*>(&u2.y));
                float2 f30 = __half22float2(*reinterpret_cast<__half2*>(&u3.x));
                float2 f31 = __half22float2(*reinterpret_cast<__half2*>(&u3.y));
                a0 += w0.x * f00.x + w1.x * f10.x + w2.x * f20.x + w3.x * f30.x;
                a1 += w0.y * f00.y + w1.y * f10.y + w2.y * f20.y + w3.y * f30.y;
                a2 += w0.z * f01.x + w1.z * f11.x + w2.z * f21.x + w3.z * f31.x;
                a3 += w0.w * f01.y + w1.w * f11.y + w2.w * f21.y + w3.w * f31.y;
            }
            for (; j < m; j++) {
                int   s0 = sm_s[wid][j];
                float4 w0 = sm_w[wid][j];
                uint2 u0 = *reinterpret_cast<const uint2*>(g_feat_h + (size_t)s0 * FDIM + lane * 4);
                float2 f00 = __half22float2(*reinterpret_cast<__half2*>(&u0.x));
                float2 f01 = __half22float2(*reinterpret_cast<__half2*>(&u0.y));
                a0 += w0.x * f00.x;
                a1 += w0.y * f00.y;
                a2 += w0.z * f01.x;
                a3 += w0.w * f01.y;
            }
            __syncwarp();
        }

#pragma unroll
        for (int off = 16; off; off >>= 1) {
            sx += __shfl_xor_sync(0xffffffffu, sx, off);
            sy += __shfl_xor_sync(0xffffffffu, sy, off);
            sz += __shfl_xor_sync(0xffffffffu, sz, off);
            sw += __shfl_xor_sync(0xffffffffu, sw, off);
        }
        float invx = 1.f / fmaxf(sx, 1e-9f);
        float invy = 1.f / fmaxf(sy, 1e-9f);
        float invz = 1.f / fmaxf(sz, 1e-9f);
        float invw = 1.f / fmaxf(sw, 1e-9f);

        float r0 = a0 * invx + resid[node * FDIM + 0  + lane] + bias[0  + lane];
        float r1 = a1 * invy + resid[node * FDIM + 32 + lane] + bias[32 + lane];
        float r2 = a2 * invz + resid[node * FDIM + 64 + lane] + bias[64 + lane];
        float r3 = a3 * invw + resid[node * FDIM + 96 + lane] + bias[96 + lane];

        if (MODE == 1) {
            out[node * FDIM + 0  + lane] = elu1(r0);
            out[node * FDIM + 32 + lane] = elu1(r1);
            out[node * FDIM + 64 + lane] = elu1(r2);
            out[node * FDIM + 96 + lane] = elu1(r3);
        } else {
            out[node * 32 + lane] = 0.25f * (r0 + r1 + r2 + r3);
        }
    }
}

// -------------------- launch ------------------------------------------------
extern "C" void kernel_launch(void* const* d_in, const int* in_sizes, int n_in,
                              void* d_out, int out_size) {
    const float* x   = (const float*)d_in[0];
    const float* W1  = (const float*)d_in[1];
    const float* al1 = (const float*)d_in[2];
    const float* ar1 = (const float*)d_in[3];
    const float* b1  = (const float*)d_in[4];
    const float* W2  = (const float*)d_in[5];
    const float* al2 = (const float*)d_in[6];
    const float* ar2 = (const float*)d_in[7];
    const float* b2  = (const float*)d_in[8];
    const int*   src = (const int*)d_in[9];
    const int*   dst = (const int*)d_in[10];
    float* out = (float*)d_out;

    float* h1 = nullptr;
    __half* wh = nullptr;
    cudaGetSymbolAddress((void**)&h1, g_h1);
    cudaGetSymbolAddress((void**)&wh, g_Wh);

    const int TB = 256;
    int nblkN = (NN + TB - 1) / TB;                 // 196
    int nblkE = (EE + TB - 1) / TB;                 // 3125
    int nWc   = (2 * FDIM * FDIM / 4 + TB - 1) / TB; // 32

    k_wconv<<<nWc, TB>>>(W1, W2);                         // 1
    k_zero_cnt<<<nblkN, TB>>>();                          // 2
    k_count<<<nblkE, TB>>>(dst);                          // 3
    k_gemm_fused<<<NGEMM, 256>>>(x, wh, al1, ar1);        // 4  <- profiled
    k_scan1<<<NSCAN, 1024>>>();                           // 5
    k_scan3<<<nblkN, TB>>>();                             // 6
    k_scatter<<<nblkE, TB>>>(src, dst);                   // 7
    k_agg<1><<<AGG_GRID, AGG_WARPS * 32>>>(x, b1, h1);    // 8
    k_gemm_fused<<<NGEMM, 256>>>(h1, wh + FDIM * FDIM, al2, ar2); // 9
    k_agg<2><<<AGG_GRID, AGG_WARPS * 32>>>(h1, b2, out);  // 10
}